// round 15
// baseline (speedup 1.0000x reference)
#include <cuda_runtime.h>
#include <cuda_fp16.h>
#include <math_constants.h>
#include <cstdint>

#define B_SZ 4
#define T_SEQ 4096
#define C_DIM 768
#define HD 64
#define NCHUNK 2

// fp16 scratch
__device__ __half g_q[B_SZ * T_SEQ * HD];
__device__ __half g_k[B_SZ * T_SEQ * HD];
__device__ __half g_vt[B_SZ * HD * T_SEQ];        // [b][h][t]
__device__ __half g_wt[3 * HD * C_DIM];           // [m][h][k]

// split-KV partials + completion flags
__device__ float g_po[NCHUNK * B_SZ * T_SEQ * HD];
__device__ float g_pl[NCHUNK * B_SZ * T_SEQ];
__device__ int g_flag[B_SZ * (T_SEQ / 64)];       // zero-init; reset after each use

#define SCALE_Q 0.1803368801111244f   // 0.125 * log2(e)

// ---------------------------------------------------------------------------
// helpers
// ---------------------------------------------------------------------------
__device__ __forceinline__ void mma16816(float c[4],
    uint32_t a0, uint32_t a1, uint32_t a2, uint32_t a3,
    uint32_t b0, uint32_t b1)
{
    asm volatile(
        "mma.sync.aligned.m16n8k16.row.col.f32.f16.f16.f32 "
        "{%0,%1,%2,%3}, {%4,%5,%6,%7}, {%8,%9}, {%0,%1,%2,%3};\n"
        : "+f"(c[0]), "+f"(c[1]), "+f"(c[2]), "+f"(c[3])
        : "r"(a0), "r"(a1), "r"(a2), "r"(a3), "r"(b0), "r"(b1));
}

__device__ __forceinline__ float ex2(float x)
{
    float y;
    asm("ex2.approx.f32 %0, %1;" : "=f"(y) : "f"(x));
    return y;
}

__device__ __forceinline__ void cp_async16(void* dst, const void* src)
{
    uint32_t s = (uint32_t)__cvta_generic_to_shared(dst);
    asm volatile("cp.async.cg.shared.global [%0], [%1], 16;\n" :: "r"(s), "l"(src));
}
#define CP_COMMIT() asm volatile("cp.async.commit_group;\n")
#define CP_WAIT1()  asm volatile("cp.async.wait_group 1;\n")
#define CP_WAIT0()  asm volatile("cp.async.wait_group 0;\n")

#define FULLMASK 0xffffffffu
#define PSTR 72
#define TILE_H (64 * PSTR)   // halves per 64x64 tile (padded)

// ---------------------------------------------------------------------------
// Kernel 0: transpose + fp16-convert weights; Wq pre-scaled. Runs once.
// ---------------------------------------------------------------------------
__global__ __launch_bounds__(256) void wt_kernel(
    const float* __restrict__ Wq,
    const float* __restrict__ Wk,
    const float* __restrict__ Wv)
{
    __shared__ __half sT[64 * 72];
    const int m = blockIdx.y;
    const int k0 = blockIdx.x * 64;
    const float* W = (m == 0) ? Wq : (m == 1) ? Wk : Wv;
    const float scl = (m == 0) ? SCALE_Q : 1.0f;
    const int tid = threadIdx.x;

    #pragma unroll
    for (int u = 0; u < 16; u++) {
        int i = tid + u * 256;
        int kk = i >> 6;
        int h = i & 63;
        sT[h * 72 + kk] = __float2half(W[(size_t)(k0 + kk) * HD + h] * scl);
    }
    __syncthreads();
    #pragma unroll
    for (int u = 0; u < 2; u++) {
        int i = tid + u * 256;
        int h = i >> 3;
        int c8 = i & 7;
        *(uint4*)&g_wt[(size_t)(m * HD + h) * C_DIM + k0 + c8 * 8] =
            *(const uint4*)&sT[h * 72 + c8 * 8];
    }
}

// ---------------------------------------------------------------------------
// Kernel 1: QKV projection, BM=64, 384 threads, 256 blocks.
// ---------------------------------------------------------------------------
__global__ __launch_bounds__(384) void proj4(const float* __restrict__ x)
{
    __shared__ __half sX[64 * PSTR];
    __shared__ __half sW[3 * 64 * PSTR];

    const int tid = threadIdx.x;
    const int warp = tid >> 5;
    const int lane = tid & 31;
    const int g = lane >> 2;
    const int t = lane & 3;
    const int m = warp >> 2;
    const int rloc = (warp & 3) * 16;
    const int row0 = blockIdx.x * 64;

    float acc[8][4];
    #pragma unroll
    for (int nt = 0; nt < 8; nt++)
        #pragma unroll
        for (int c = 0; c < 4; c++) acc[nt][c] = 0.f;

    const float4* x4 = (const float4*)x;

    for (int k0 = 0; k0 < C_DIM; k0 += 64) {
        __syncthreads();
        for (int i = tid; i < 1536; i += 384) {
            int mm = i >> 9;
            int h = (i >> 3) & 63;
            int c8 = i & 7;
            cp_async16(&sW[(mm * 64 + h) * PSTR + c8 * 8],
                       &g_wt[(size_t)(mm * HD + h) * C_DIM + k0 + c8 * 8]);
        }
        CP_COMMIT();
        for (int i = tid; i < 1024; i += 384) {
            int r = i >> 4;
            int k4 = i & 15;
            float4 v = x4[(size_t)(row0 + r) * (C_DIM / 4) + (k0 >> 2) + k4];
            __half2* dst = (__half2*)&sX[r * PSTR + k4 * 4];
            dst[0] = __floats2half2_rn(v.x, v.y);
            dst[1] = __floats2half2_rn(v.z, v.w);
        }
        CP_WAIT0();
        __syncthreads();

        #pragma unroll
        for (int ks = 0; ks < 4; ks++) {
            int ca = ks * 16 + t * 2;
            uint32_t A0 = *(const uint32_t*)&sX[(rloc + g) * PSTR + ca];
            uint32_t A1 = *(const uint32_t*)&sX[(rloc + g + 8) * PSTR + ca];
            uint32_t A2 = *(const uint32_t*)&sX[(rloc + g) * PSTR + ca + 8];
            uint32_t A3 = *(const uint32_t*)&sX[(rloc + g + 8) * PSTR + ca + 8];
            #pragma unroll
            for (int nt = 0; nt < 8; nt++) {
                uint32_t B0 = *(const uint32_t*)&sW[(m * 64 + nt * 8 + g) * PSTR + ca];
                uint32_t B1 = *(const uint32_t*)&sW[(m * 64 + nt * 8 + g) * PSTR + ca + 8];
                mma16816(acc[nt], A0, A1, A2, A3, B0, B1);
            }
        }
    }

    __syncthreads();

    __half* sVst = sX;

    if (m < 2) {
        __half* dst = (m == 0) ? g_q : g_k;
        int rowg = row0 + rloc + g;
        #pragma unroll
        for (int nt = 0; nt < 8; nt++) {
            int col = nt * 8 + t * 2;
            *(__half2*)&dst[(size_t)rowg * HD + col] =
                __floats2half2_rn(acc[nt][0], acc[nt][1]);
            *(__half2*)&dst[(size_t)(rowg + 8) * HD + col] =
                __floats2half2_rn(acc[nt][2], acc[nt][3]);
        }
    } else {
        #pragma unroll
        for (int nt = 0; nt < 8; nt++) {
            int c = nt * 8 + t * 2;
            sVst[c * PSTR + rloc + g]           = __float2half(acc[nt][0]);
            sVst[(c + 1) * PSTR + rloc + g]     = __float2half(acc[nt][1]);
            sVst[c * PSTR + rloc + g + 8]       = __float2half(acc[nt][2]);
            sVst[(c + 1) * PSTR + rloc + g + 8] = __float2half(acc[nt][3]);
        }
    }
    __syncthreads();

    const int bb = row0 >> 12;
    const int t0 = row0 & 4095;
    for (int i = tid; i < 512; i += 384) {
        int h = i >> 3;
        int c8 = i & 7;
        *(uint4*)(g_vt + (size_t)bb * HD * T_SEQ + (size_t)h * T_SEQ + t0 + c8 * 8) =
            *(const uint4*)&sVst[h * PSTR + c8 * 8];
    }
}

// ---------------------------------------------------------------------------
// Kernel 2: split-KV flash (R10 body), Q fragments hoisted to registers via
// scalar LDS; smem = 6 tiles (3K+3V, 54KB) -> 4 CTAs/SM, single wave.
// Q stages through the K-stage-2 slot; the loop's first __syncthreads orders
// all pre-loop Q reads before any stage-2 K load overwrites it.
// ---------------------------------------------------------------------------
__global__ __launch_bounds__(128) void flash12(float* __restrict__ out)
{
    extern __shared__ __half smem[];
    __half* sK0 = smem;                 // 3 K stages; stage 2 doubles as Q staging
    __half* sV0 = smem + 3 * TILE_H;    // 3 V stages
    __half* sQ = sK0 + 2 * TILE_H;
    __shared__ int s_old;

    const int tid = threadIdx.x;
    const int warp = tid >> 5;
    const int lane = tid & 31;
    const int g = lane >> 2;
    const int t = lane & 3;
    const int m0 = warp * 16;
    const int iq = (T_SEQ / 64 - 1) - blockIdx.x;   // heavy-first
    const int chunk = blockIdx.y;
    const int b = blockIdx.z;

    const __half* gk_base = g_k + (size_t)b * T_SEQ * HD;
    const __half* gvt_base = g_vt + (size_t)b * HD * T_SEQ;

    // stage Q, then lift fragments into registers with the SAME scalar-LDS
    // pattern the R10 loop used per-iteration.
    {
        const uint4* gq = (const uint4*)(g_q + ((size_t)b * T_SEQ + iq * 64) * HD);
        #pragma unroll
        for (int u = 0; u < 4; u++) {
            int i = tid + u * 128;
            int r = i >> 3, c8 = i & 7;
            *(uint4*)&sQ[r * PSTR + c8 * 8] = gq[r * 8 + c8];
        }
    }
    __syncthreads();

    const int rA = (m0 + g) * PSTR;
    const int rB = (m0 + g + 8) * PSTR;
    uint32_t qa[4][4];
    #pragma unroll
    for (int ks = 0; ks < 4; ks++) {
        int ca = ks * 16 + t * 2;
        qa[ks][0] = *(const uint32_t*)&sQ[rA + ca];
        qa[ks][1] = *(const uint32_t*)&sQ[rB + ca];
        qa[ks][2] = *(const uint32_t*)&sQ[rA + ca + 8];
        qa[ks][3] = *(const uint32_t*)&sQ[rB + ca + 8];
    }

    auto loadKV = [&](int j, int s) {
        __half* dK = sK0 + s * TILE_H;
        __half* dV = sV0 + s * TILE_H;
        #pragma unroll
        for (int u = 0; u < 4; u++) {
            int i = tid + u * 128;
            int r = i >> 3, c8 = i & 7;
            cp_async16(&dK[r * PSTR + c8 * 8],
                       gk_base + ((size_t)(j * 64 + r) * HD) + c8 * 8);
        }
        #pragma unroll
        for (int u = 0; u < 4; u++) {
            int i = tid + u * 128;
            int h = i >> 3, c8 = i & 7;
            cp_async16(&dV[h * PSTR + c8 * 8],
                       gvt_base + (size_t)h * T_SEQ + j * 64 + c8 * 8);
        }
    };

    float oc[8][4];
    #pragma unroll
    for (int nt = 0; nt < 8; nt++)
        #pragma unroll
        for (int c = 0; c < 4; c++) oc[nt][c] = 0.f;
    float l0 = 0.f, l1 = 0.f;

    const int row0i = m0 + g;
    const int row1i = m0 + g + 8;

    const int n = (chunk <= iq) ? ((iq - chunk) / NCHUNK + 1) : 0;

    if (n > 0) { loadKV(chunk, 0); CP_COMMIT(); }
    if (n > 1) { loadKV(chunk + NCHUNK, 1); CP_COMMIT(); }

    for (int cnt = 0; cnt < n; cnt++) {
        const int j = chunk + cnt * NCHUNK;
        if (cnt + 1 < n) { CP_WAIT1(); } else { CP_WAIT0(); }
        __syncthreads();
        if (cnt + 2 < n) {
            loadKV(j + 2 * NCHUNK, (cnt + 2) % 3);
            CP_COMMIT();
        }

        const __half* bK = sK0 + (cnt % 3) * TILE_H;
        const __half* bV = sV0 + (cnt % 3) * TILE_H;

        float sc[8][4];
        #pragma unroll
        for (int nt = 0; nt < 8; nt++)
            #pragma unroll
            for (int c = 0; c < 4; c++) sc[nt][c] = 0.f;

        #pragma unroll
        for (int ks = 0; ks < 4; ks++) {
            int ca = ks * 16 + t * 2;
            #pragma unroll
            for (int nt = 0; nt < 8; nt++) {
                uint32_t B0 = *(const uint32_t*)&bK[(nt * 8 + g) * PSTR + ca];
                uint32_t B1 = *(const uint32_t*)&bK[(nt * 8 + g) * PSTR + ca + 8];
                mma16816(sc[nt], qa[ks][0], qa[ks][1], qa[ks][2], qa[ks][3], B0, B1);
            }
        }

        if (j == iq) {
            #pragma unroll
            for (int nt = 0; nt < 8; nt++) {
                int cl = nt * 8 + t * 2;
                if (cl     > row0i) sc[nt][0] = -CUDART_INF_F;
                if (cl + 1 > row0i) sc[nt][1] = -CUDART_INF_F;
                if (cl     > row1i) sc[nt][2] = -CUDART_INF_F;
                if (cl + 1 > row1i) sc[nt][3] = -CUDART_INF_F;
            }
        }

        uint32_t pa[4][4];
        #pragma unroll
        for (int nt = 0; nt < 8; nt++) {
            float p0 = ex2(sc[nt][0]);
            float p1 = ex2(sc[nt][1]);
            float p2 = ex2(sc[nt][2]);
            float p3 = ex2(sc[nt][3]);
            l0 += p0 + p1;
            l1 += p2 + p3;
            __half2 h01 = __floats2half2_rn(p0, p1);
            __half2 h23 = __floats2half2_rn(p2, p3);
            int ks = nt >> 1;
            if ((nt & 1) == 0) {
                pa[ks][0] = *(uint32_t*)&h01;
                pa[ks][1] = *(uint32_t*)&h23;
            } else {
                pa[ks][2] = *(uint32_t*)&h01;
                pa[ks][3] = *(uint32_t*)&h23;
            }
        }

        #pragma unroll
        for (int ks = 0; ks < 4; ks++) {
            int ca = ks * 16 + t * 2;
            #pragma unroll
            for (int nt = 0; nt < 8; nt++) {
                uint32_t B0 = *(const uint32_t*)&bV[(nt * 8 + g) * PSTR + ca];
                uint32_t B1 = *(const uint32_t*)&bV[(nt * 8 + g) * PSTR + ca + 8];
                mma16816(oc[nt], pa[ks][0], pa[ks][1], pa[ks][2], pa[ks][3], B0, B1);
            }
        }
    }

    l0 += __shfl_xor_sync(FULLMASK, l0, 1);
    l0 += __shfl_xor_sync(FULLMASK, l0, 2);
    l1 += __shfl_xor_sync(FULLMASK, l1, 1);
    l1 += __shfl_xor_sync(FULLMASK, l1, 2);

    const size_t NR = (size_t)B_SZ * T_SEQ;
    size_t rowg0 = (size_t)b * T_SEQ + iq * 64 + row0i;
    size_t rowg1 = rowg0 + 8;

    // write own partial
    float* po = g_po + (size_t)chunk * NR * HD;
    #pragma unroll
    for (int nt = 0; nt < 8; nt++) {
        int cl = nt * 8 + t * 2;
        *(float2*)&po[rowg0 * HD + cl] = make_float2(oc[nt][0], oc[nt][1]);
        *(float2*)&po[rowg1 * HD + cl] = make_float2(oc[nt][2], oc[nt][3]);
    }
    if (t == 0) {
        g_pl[(size_t)chunk * NR + rowg0] = l0;
        g_pl[(size_t)chunk * NR + rowg1] = l1;
    }

    // handshake: second-arriving CTA merges and writes `out` directly
    __threadfence();
    __syncthreads();
    if (tid == 0) s_old = atomicAdd(&g_flag[b * (T_SEQ / 64) + iq], 1);
    __syncthreads();

    if (s_old == 1) {
        __threadfence();   // acquire partner's stores
        const float* pp = g_po + (size_t)(chunk ^ 1) * NR * HD;
        float lo0 = g_pl[(size_t)(chunk ^ 1) * NR + rowg0];
        float lo1 = g_pl[(size_t)(chunk ^ 1) * NR + rowg1];
        float inv0 = 1.f / (l0 + lo0);
        float inv1 = 1.f / (l1 + lo1);
        #pragma unroll
        for (int nt = 0; nt < 8; nt++) {
            int cl = nt * 8 + t * 2;
            float2 p0v = *(const float2*)&pp[rowg0 * HD + cl];
            float2 p1v = *(const float2*)&pp[rowg1 * HD + cl];
            *(float2*)&out[rowg0 * HD + cl] = make_float2(
                (oc[nt][0] + p0v.x) * inv0, (oc[nt][1] + p0v.y) * inv0);
            *(float2*)&out[rowg1 * HD + cl] = make_float2(
                (oc[nt][2] + p1v.x) * inv1, (oc[nt][3] + p1v.y) * inv1);
        }
        if (tid == 0) atomicExch(&g_flag[b * (T_SEQ / 64) + iq], 0);
    }
}

extern "C" void kernel_launch(void* const* d_in, const int* in_sizes, int n_in,
                              void* d_out, int out_size)
{
    const float* x  = (const float*)d_in[0];
    const float* Wq = (const float*)d_in[1];
    const float* Wk = (const float*)d_in[2];
    const float* Wv = (const float*)d_in[3];
    float* out = (float*)d_out;

    wt_kernel<<<dim3(C_DIM / 64, 3), 256>>>(Wq, Wk, Wv);
    proj4<<<(B_SZ * T_SEQ) / 64, 384>>>(x);

    size_t smem_bytes = (size_t)6 * TILE_H * sizeof(__half);   // 55296
    cudaFuncSetAttribute(flash12, cudaFuncAttributeMaxDynamicSharedMemorySize,
                         (int)smem_bytes);
    flash12<<<dim3(T_SEQ / 64, NCHUNK, B_SZ), 128, smem_bytes>>>(out);
}

// round 16
// speedup vs baseline: 1.2148x; 1.2148x over previous
#include <cuda_runtime.h>
#include <cuda_fp16.h>
#include <math_constants.h>
#include <cstdint>

#define B_SZ 4
#define T_SEQ 4096
#define C_DIM 768
#define HD 64
#define NCHUNK 2

// fp16 scratch
__device__ __half g_q[B_SZ * T_SEQ * HD];
__device__ __half g_k[B_SZ * T_SEQ * HD];
__device__ __half g_vt[B_SZ * HD * T_SEQ];        // [b][h][t]
__device__ __half g_wt[3 * HD * C_DIM];           // [m][h][k]

// split-KV partials + completion flags
__device__ float g_po[NCHUNK * B_SZ * T_SEQ * HD];
__device__ float g_pl[NCHUNK * B_SZ * T_SEQ];
__device__ int g_flag[B_SZ * (T_SEQ / 64)];       // zero-init; reset after each use

#define SCALE_Q 0.1803368801111244f   // 0.125 * log2(e)

// ---------------------------------------------------------------------------
// helpers
// ---------------------------------------------------------------------------
__device__ __forceinline__ void mma16816(float c[4],
    uint32_t a0, uint32_t a1, uint32_t a2, uint32_t a3,
    uint32_t b0, uint32_t b1)
{
    asm volatile(
        "mma.sync.aligned.m16n8k16.row.col.f32.f16.f16.f32 "
        "{%0,%1,%2,%3}, {%4,%5,%6,%7}, {%8,%9}, {%0,%1,%2,%3};\n"
        : "+f"(c[0]), "+f"(c[1]), "+f"(c[2]), "+f"(c[3])
        : "r"(a0), "r"(a1), "r"(a2), "r"(a3), "r"(b0), "r"(b1));
}

__device__ __forceinline__ float ex2(float x)
{
    float y;
    asm("ex2.approx.f32 %0, %1;" : "=f"(y) : "f"(x));
    return y;
}

__device__ __forceinline__ void cp_async16(void* dst, const void* src)
{
    uint32_t s = (uint32_t)__cvta_generic_to_shared(dst);
    asm volatile("cp.async.cg.shared.global [%0], [%1], 16;\n" :: "r"(s), "l"(src));
}
#define CP_COMMIT() asm volatile("cp.async.commit_group;\n")
#define CP_WAIT1()  asm volatile("cp.async.wait_group 1;\n")
#define CP_WAIT0()  asm volatile("cp.async.wait_group 0;\n")

#define FULLMASK 0xffffffffu
#define PSTR 72
#define TILE_H (64 * PSTR)   // halves per 64x64 tile (padded)

// ---------------------------------------------------------------------------
// Kernel 0: transpose + fp16-convert weights; Wq pre-scaled. Runs once.
// (EXACT R10 form.)
// ---------------------------------------------------------------------------
__global__ __launch_bounds__(256) void wt_kernel(
    const float* __restrict__ Wq,
    const float* __restrict__ Wk,
    const float* __restrict__ Wv)
{
    __shared__ __half sT[64 * 72];
    const int m = blockIdx.y;
    const int k0 = blockIdx.x * 64;
    const float* W = (m == 0) ? Wq : (m == 1) ? Wk : Wv;
    const float scl = (m == 0) ? SCALE_Q : 1.0f;
    const int tid = threadIdx.x;

    #pragma unroll
    for (int u = 0; u < 16; u++) {
        int i = tid + u * 256;
        int kk = i >> 6;
        int h = i & 63;
        sT[h * 72 + kk] = __float2half(W[(size_t)(k0 + kk) * HD + h] * scl);
    }
    __syncthreads();
    #pragma unroll
    for (int u = 0; u < 2; u++) {
        int i = tid + u * 256;
        int h = i >> 3;
        int c8 = i & 7;
        *(uint4*)&g_wt[(size_t)(m * HD + h) * C_DIM + k0 + c8 * 8] =
            *(const uint4*)&sT[h * 72 + c8 * 8];
    }
}

// ---------------------------------------------------------------------------
// Kernel 1: QKV projection, software-pipelined. BM=64, 384 threads, 256 blocks.
// x LDG'd 2 chunks ahead into registers; W cp.async'd 1 chunk ahead;
// double-buffered smem (74KB dynamic); ONE __syncthreads per chunk.
// ---------------------------------------------------------------------------
#define NKCH (C_DIM / 64)   // 12

__global__ __launch_bounds__(384) void proj6(const float* __restrict__ x)
{
    extern __shared__ __half psmem[];
    __half* sXb0 = psmem;                       // 64*PSTR
    __half* sXb1 = psmem + TILE_H;              // 64*PSTR
    __half* sWb0 = psmem + 2 * TILE_H;          // 3*64*PSTR
    __half* sWb1 = psmem + 5 * TILE_H;          // 3*64*PSTR

    const int tid = threadIdx.x;
    const int warp = tid >> 5;
    const int lane = tid & 31;
    const int g = lane >> 2;
    const int t = lane & 3;
    const int m = warp >> 2;
    const int rloc = (warp & 3) * 16;
    const int row0 = blockIdx.x * 64;

    const float4* x4 = (const float4*)x;

    float acc[8][4];
    #pragma unroll
    for (int nt = 0; nt < 8; nt++)
        #pragma unroll
        for (int c = 0; c < 4; c++) acc[nt][c] = 0.f;

    auto loadW = [&](int c, __half* dst) {
        int k0 = c * 64;
        for (int i = tid; i < 1536; i += 384) {
            int mm = i >> 9;
            int h = (i >> 3) & 63;
            int c8 = i & 7;
            cp_async16(&dst[(mm * 64 + h) * PSTR + c8 * 8],
                       &g_wt[(size_t)(mm * HD + h) * C_DIM + k0 + c8 * 8]);
        }
        CP_COMMIT();
    };
    auto loadXreg = [&](int c, float4 xr[3]) {
        int k0 = c * 64;
        #pragma unroll
        for (int u = 0; u < 3; u++) {
            int i = tid + u * 384;
            if (i < 1024) {
                int r = i >> 4;
                int k4 = i & 15;
                xr[u] = x4[(size_t)(row0 + r) * (C_DIM / 4) + (k0 >> 2) + k4];
            }
        }
    };
    auto stsX = [&](__half* dst, const float4 xr[3]) {
        #pragma unroll
        for (int u = 0; u < 3; u++) {
            int i = tid + u * 384;
            if (i < 1024) {
                int r = i >> 4;
                int k4 = i & 15;
                __half2* d = (__half2*)&dst[r * PSTR + k4 * 4];
                d[0] = __floats2half2_rn(xr[u].x, xr[u].y);
                d[1] = __floats2half2_rn(xr[u].z, xr[u].w);
            }
        }
    };

    // prologue: chunk0 x staged, W0 in flight, chunk1 x in regs
    float4 xr_nxt[3];
    {
        float4 xr0[3];
        loadXreg(0, xr0);
        loadW(0, sWb0);
        stsX(sXb0, xr0);
        loadXreg(1, xr_nxt);
    }

    for (int c = 0; c < NKCH; c++) {
        CP_WAIT0();          // W chunk c landed
        __syncthreads();     // publish sX/sW buf c; retire reads of buf c-1
        if (c + 1 < NKCH)
            loadW(c + 1, ((c + 1) & 1) ? sWb1 : sWb0);

        const __half* bX = (c & 1) ? sXb1 : sXb0;
        const __half* bW = (c & 1) ? sWb1 : sWb0;

        #pragma unroll
        for (int ks = 0; ks < 4; ks++) {
            int ca = ks * 16 + t * 2;
            uint32_t A0 = *(const uint32_t*)&bX[(rloc + g) * PSTR + ca];
            uint32_t A1 = *(const uint32_t*)&bX[(rloc + g + 8) * PSTR + ca];
            uint32_t A2 = *(const uint32_t*)&bX[(rloc + g) * PSTR + ca + 8];
            uint32_t A3 = *(const uint32_t*)&bX[(rloc + g + 8) * PSTR + ca + 8];
            #pragma unroll
            for (int nt = 0; nt < 8; nt++) {
                uint32_t B0 = *(const uint32_t*)&bW[(m * 64 + nt * 8 + g) * PSTR + ca];
                uint32_t B1 = *(const uint32_t*)&bW[(m * 64 + nt * 8 + g) * PSTR + ca + 8];
                mma16816(acc[nt], A0, A1, A2, A3, B0, B1);
            }
        }

        if (c + 1 < NKCH)
            stsX(((c + 1) & 1) ? sXb1 : sXb0, xr_nxt);   // buf retired at this iter's sync
        if (c + 2 < NKCH)
            loadXreg(c + 2, xr_nxt);
    }

    __syncthreads();

    __half* sVst = sXb0;   // staging: [h][tloc] stride PSTR

    if (m < 2) {
        __half* dst = (m == 0) ? g_q : g_k;
        int rowg = row0 + rloc + g;
        #pragma unroll
        for (int nt = 0; nt < 8; nt++) {
            int col = nt * 8 + t * 2;
            *(__half2*)&dst[(size_t)rowg * HD + col] =
                __floats2half2_rn(acc[nt][0], acc[nt][1]);
            *(__half2*)&dst[(size_t)(rowg + 8) * HD + col] =
                __floats2half2_rn(acc[nt][2], acc[nt][3]);
        }
    } else {
        #pragma unroll
        for (int nt = 0; nt < 8; nt++) {
            int c = nt * 8 + t * 2;
            sVst[c * PSTR + rloc + g]           = __float2half(acc[nt][0]);
            sVst[(c + 1) * PSTR + rloc + g]     = __float2half(acc[nt][1]);
            sVst[c * PSTR + rloc + g + 8]       = __float2half(acc[nt][2]);
            sVst[(c + 1) * PSTR + rloc + g + 8] = __float2half(acc[nt][3]);
        }
    }
    __syncthreads();

    const int bb = row0 >> 12;
    const int t0 = row0 & 4095;
    for (int i = tid; i < 512; i += 384) {
        int h = i >> 3;
        int c8 = i & 7;
        *(uint4*)(g_vt + (size_t)bb * HD * T_SEQ + (size_t)h * T_SEQ + t0 + c8 * 8) =
            *(const uint4*)&sVst[h * PSTR + c8 * 8];
    }
}

// ---------------------------------------------------------------------------
// Kernel 2: split-KV flash (EXACT R10 form): static-max softmax, 3-stage
// cp.async pipeline, fused combine writing `out` directly.
// Grid (64, NCHUNK, B), 128 threads, 63KB dynamic smem.
// ---------------------------------------------------------------------------
__global__ __launch_bounds__(128) void flash8(float* __restrict__ out)
{
    extern __shared__ __half smem[];
    __half* sQ = smem;
    __half* sK0 = sQ + TILE_H;
    __half* sV0 = sK0 + 3 * TILE_H;
    __shared__ int s_old;

    const int tid = threadIdx.x;
    const int warp = tid >> 5;
    const int lane = tid & 31;
    const int g = lane >> 2;
    const int t = lane & 3;
    const int m0 = warp * 16;
    const int iq = (T_SEQ / 64 - 1) - blockIdx.x;   // heavy-first
    const int chunk = blockIdx.y;
    const int b = blockIdx.z;

    const __half* gk_base = g_k + (size_t)b * T_SEQ * HD;
    const __half* gvt_base = g_vt + (size_t)b * HD * T_SEQ;

    {
        const uint4* gq = (const uint4*)(g_q + ((size_t)b * T_SEQ + iq * 64) * HD);
        #pragma unroll
        for (int u = 0; u < 4; u++) {
            int i = tid + u * 128;
            int r = i >> 3, c8 = i & 7;
            *(uint4*)&sQ[r * PSTR + c8 * 8] = gq[r * 8 + c8];
        }
    }

    auto loadKV = [&](int j, int s) {
        __half* dK = sK0 + s * TILE_H;
        __half* dV = sV0 + s * TILE_H;
        #pragma unroll
        for (int u = 0; u < 4; u++) {
            int i = tid + u * 128;
            int r = i >> 3, c8 = i & 7;
            cp_async16(&dK[r * PSTR + c8 * 8],
                       gk_base + ((size_t)(j * 64 + r) * HD) + c8 * 8);
        }
        #pragma unroll
        for (int u = 0; u < 4; u++) {
            int i = tid + u * 128;
            int h = i >> 3, c8 = i & 7;
            cp_async16(&dV[h * PSTR + c8 * 8],
                       gvt_base + (size_t)h * T_SEQ + j * 64 + c8 * 8);
        }
    };

    float oc[8][4];
    #pragma unroll
    for (int nt = 0; nt < 8; nt++)
        #pragma unroll
        for (int c = 0; c < 4; c++) oc[nt][c] = 0.f;
    float l0 = 0.f, l1 = 0.f;

    const int rA = (m0 + g) * PSTR;
    const int rB = (m0 + g + 8) * PSTR;
    const int row0i = m0 + g;
    const int row1i = m0 + g + 8;

    const int n = (chunk <= iq) ? ((iq - chunk) / NCHUNK + 1) : 0;

    if (n > 0) { loadKV(chunk, 0); CP_COMMIT(); }
    if (n > 1) { loadKV(chunk + NCHUNK, 1); CP_COMMIT(); }

    for (int cnt = 0; cnt < n; cnt++) {
        const int j = chunk + cnt * NCHUNK;
        if (cnt + 1 < n) { CP_WAIT1(); } else { CP_WAIT0(); }
        __syncthreads();
        if (cnt + 2 < n) {
            loadKV(j + 2 * NCHUNK, (cnt + 2) % 3);
            CP_COMMIT();
        }

        const __half* bK = sK0 + (cnt % 3) * TILE_H;
        const __half* bV = sV0 + (cnt % 3) * TILE_H;

        float sc[8][4];
        #pragma unroll
        for (int nt = 0; nt < 8; nt++)
            #pragma unroll
            for (int c = 0; c < 4; c++) sc[nt][c] = 0.f;

        #pragma unroll
        for (int ks = 0; ks < 4; ks++) {
            int ca = ks * 16 + t * 2;
            uint32_t A0 = *(const uint32_t*)&sQ[rA + ca];
            uint32_t A1 = *(const uint32_t*)&sQ[rB + ca];
            uint32_t A2 = *(const uint32_t*)&sQ[rA + ca + 8];
            uint32_t A3 = *(const uint32_t*)&sQ[rB + ca + 8];
            #pragma unroll
            for (int nt = 0; nt < 8; nt++) {
                uint32_t B0 = *(const uint32_t*)&bK[(nt * 8 + g) * PSTR + ca];
                uint32_t B1 = *(const uint32_t*)&bK[(nt * 8 + g) * PSTR + ca + 8];
                mma16816(sc[nt], A0, A1, A2, A3, B0, B1);
            }
        }

        if (j == iq) {
            #pragma unroll
            for (int nt = 0; nt < 8; nt++) {
                int cl = nt * 8 + t * 2;
                if (cl     > row0i) sc[nt][0] = -CUDART_INF_F;
                if (cl + 1 > row0i) sc[nt][1] = -CUDART_INF_F;
                if (cl     > row1i) sc[nt][2] = -CUDART_INF_F;
                if (cl + 1 > row1i) sc[nt][3] = -CUDART_INF_F;
            }
        }

        uint32_t pa[4][4];
        #pragma unroll
        for (int nt = 0; nt < 8; nt++) {
            float p0 = ex2(sc[nt][0]);
            float p1 = ex2(sc[nt][1]);
            float p2 = ex2(sc[nt][2]);
            float p3 = ex2(sc[nt][3]);
            l0 += p0 + p1;
            l1 += p2 + p3;
            __half2 h01 = __floats2half2_rn(p0, p1);
            __half2 h23 = __floats2half2_rn(p2, p3);
            int ks = nt >> 1;
            if ((nt & 1) == 0) {
                pa[ks][0] = *(uint32_t*)&h01;
                pa[ks][1] = *(uint32_t*)&h23;
            } else {
                pa[ks][2] = *(uint32_t*)&h01;
                pa[ks][3] = *(uint32_t*)&h23;
            }
        }

        #pragma unroll
        for (int ks = 0; ks < 4; ks++) {
            int ca = ks * 16 + t * 2;
            #pragma unroll
            for (int nt = 0; nt < 8; nt++) {
                uint32_t B0 = *(const uint32_t*)&bV[(nt * 8 + g) * PSTR + ca];
                uint32_t B1 = *(const uint32_t*)&bV[(nt * 8 + g) * PSTR + ca + 8];
                mma16816(oc[nt], pa[ks][0], pa[ks][1], pa[ks][2], pa[ks][3], B0, B1);
            }
        }
    }

    l0 += __shfl_xor_sync(FULLMASK, l0, 1);
    l0 += __shfl_xor_sync(FULLMASK, l0, 2);
    l1 += __shfl_xor_sync(FULLMASK, l1, 1);
    l1 += __shfl_xor_sync(FULLMASK, l1, 2);

    const size_t NR = (size_t)B_SZ * T_SEQ;
    size_t rowg0 = (size_t)b * T_SEQ + iq * 64 + row0i;
    size_t rowg1 = rowg0 + 8;

    // write own partial
    float* po = g_po + (size_t)chunk * NR * HD;
    #pragma unroll
    for (int nt = 0; nt < 8; nt++) {
        int cl = nt * 8 + t * 2;
        *(float2*)&po[rowg0 * HD + cl] = make_float2(oc[nt][0], oc[nt][1]);
        *(float2*)&po[rowg1 * HD + cl] = make_float2(oc[nt][2], oc[nt][3]);
    }
    if (t == 0) {
        g_pl[(size_t)chunk * NR + rowg0] = l0;
        g_pl[(size_t)chunk * NR + rowg1] = l1;
    }

    // handshake: second-arriving CTA merges and writes `out` directly
    __threadfence();
    __syncthreads();
    if (tid == 0) s_old = atomicAdd(&g_flag[b * (T_SEQ / 64) + iq], 1);
    __syncthreads();

    if (s_old == 1) {
        __threadfence();   // acquire partner's stores
        const float* pp = g_po + (size_t)(chunk ^ 1) * NR * HD;
        float lo0 = g_pl[(size_t)(chunk ^ 1) * NR + rowg0];
        float lo1 = g_pl[(size_t)(chunk ^ 1) * NR + rowg1];
        float inv0 = 1.f / (l0 + lo0);
        float inv1 = 1.f / (l1 + lo1);
        #pragma unroll
        for (int nt = 0; nt < 8; nt++) {
            int cl = nt * 8 + t * 2;
            float2 p0v = *(const float2*)&pp[rowg0 * HD + cl];
            float2 p1v = *(const float2*)&pp[rowg1 * HD + cl];
            *(float2*)&out[rowg0 * HD + cl] = make_float2(
                (oc[nt][0] + p0v.x) * inv0, (oc[nt][1] + p0v.y) * inv0);
            *(float2*)&out[rowg1 * HD + cl] = make_float2(
                (oc[nt][2] + p1v.x) * inv1, (oc[nt][3] + p1v.y) * inv1);
        }
        if (tid == 0) atomicExch(&g_flag[b * (T_SEQ / 64) + iq], 0);
    }
}

extern "C" void kernel_launch(void* const* d_in, const int* in_sizes, int n_in,
                              void* d_out, int out_size)
{
    const float* x  = (const float*)d_in[0];
    const float* Wq = (const float*)d_in[1];
    const float* Wk = (const float*)d_in[2];
    const float* Wv = (const float*)d_in[3];
    float* out = (float*)d_out;

    wt_kernel<<<dim3(C_DIM / 64, 3), 256>>>(Wq, Wk, Wv);

    size_t proj_smem = (size_t)8 * TILE_H * sizeof(__half);    // 73728
    cudaFuncSetAttribute(proj6, cudaFuncAttributeMaxDynamicSharedMemorySize,
                         (int)proj_smem);
    proj6<<<(B_SZ * T_SEQ) / 64, 384, proj_smem>>>(x);

    size_t smem_bytes = (size_t)7 * TILE_H * sizeof(__half);   // 64512
    cudaFuncSetAttribute(flash8, cudaFuncAttributeMaxDynamicSharedMemorySize,
                         (int)smem_bytes);
    flash8<<<dim3(T_SEQ / 64, NCHUNK, B_SZ), 128, smem_bytes>>>(out);
}